// round 15
// baseline (speedup 1.0000x reference)
#include <cuda_runtime.h>
#include <cuda_bf16.h>

#define Bdim 64
#define Hdim 64
#define Wdim 64
#define NPIX (Bdim * Hdim * Wdim)
#define TSTEPS 60
#define NROWS (Bdim * Hdim)     // 4096 row-tiles
#define GRID_P 592              // 148 SMs x 4 CTAs

typedef unsigned int u32;

__device__ float g_bufs[2][NPIX * 16];

// Weight fragment images, uint4 = {B0hi, B1hi, B0lo, B1lo} (one MMA B-frag pair).
__device__ __align__(16) uint4 cW4_g[9][128][4];     // [tap][n][qt]
__device__ __align__(16) uint4 w14_g[4][8][64][4];   // [quarter][kt][nl][qt]
__device__ __align__(16) uint4 w24_g[16][16][4];     // [n][kt2][qt]

__device__ __forceinline__ void splitpk(float x0, float x1, u32& hi, u32& lo) {
    u32 h;
    asm("cvt.rn.bf16x2.f32 %0, %1, %2;" : "=r"(h) : "f"(x1), "f"(x0));
    float r0 = x0 - __uint_as_float(h << 16);
    float r1 = x1 - __uint_as_float(h & 0xFFFF0000u);
    u32 l;
    asm("cvt.rn.bf16x2.f32 %0, %1, %2;" : "=r"(l) : "f"(r1), "f"(r0));
    hi = h; lo = l;
}

__device__ __forceinline__ void mma_bf(float* c, u32 a0, u32 a1, u32 a2, u32 a3,
                                       u32 b0, u32 b1) {
    asm volatile(
        "mma.sync.aligned.m16n8k16.row.col.f32.bf16.bf16.f32 "
        "{%0,%1,%2,%3}, {%4,%5,%6,%7}, {%8,%9}, {%0,%1,%2,%3};"
        : "+f"(c[0]), "+f"(c[1]), "+f"(c[2]), "+f"(c[3])
        : "r"(a0), "r"(a1), "r"(a2), "r"(a3), "r"(b0), "r"(b1));
}

// ---------------- prep: build fragment images (once) ----------------
__global__ void nca_prep(const float* __restrict__ cw, const float* __restrict__ w1,
                         const float* __restrict__ w2) {
    int idx = blockIdx.x * blockDim.x + threadIdx.x;
    if (idx < 4608) {                         // conv: 9 tap x 128 n x 4 qt
        int tap = idx >> 9, rem = idx & 511;
        int n = rem >> 2, qt = rem & 3;
        int k0 = 16 * tap + 2 * qt;
        float v0 = cw[k0 * 128 + n],       v1 = cw[(k0 + 1) * 128 + n];
        float v2 = cw[(k0 + 8) * 128 + n], v3 = cw[(k0 + 9) * 128 + n];
        u32 b0h, b0l, b1h, b1l;
        splitpk(v0, v1, b0h, b0l); splitpk(v2, v3, b1h, b1l);
        cW4_g[tap][n][qt] = make_uint4(b0h, b1h, b0l, b1l);
    } else if (idx < 4608 + 8192) {           // w1: 4 q x 8 kt x 64 nl x 4 qt
        int i = idx - 4608;
        int q = i >> 11, rem = i & 2047;
        int kt = rem >> 8, r2 = rem & 255, nl = r2 >> 2, qt = r2 & 3;
        int n = 64 * q + nl, k0 = 16 * kt + 2 * qt;
        float v0 = w1[k0 * 256 + n],       v1 = w1[(k0 + 1) * 256 + n];
        float v2 = w1[(k0 + 8) * 256 + n], v3 = w1[(k0 + 9) * 256 + n];
        u32 b0h, b0l, b1h, b1l;
        splitpk(v0, v1, b0h, b0l); splitpk(v2, v3, b1h, b1l);
        w14_g[q][kt][nl][qt] = make_uint4(b0h, b1h, b0l, b1l);
    } else if (idx < 4608 + 8192 + 1024) {    // w2: 16 n x 16 kt2 x 4 qt
        int i = idx - 12800;
        int n = i >> 6, r2 = i & 63, kt = r2 >> 2, qt = r2 & 3;
        int k0 = 16 * kt + 2 * qt;
        float v0 = w2[k0 * 16 + n],       v1 = w2[(k0 + 1) * 16 + n];
        float v2 = w2[(k0 + 8) * 16 + n], v3 = w2[(k0 + 9) * 16 + n];
        u32 b0h, b0l, b1h, b1l;
        splitpk(v0, v1, b0h, b0l); splitpk(v2, v3, b1h, b1l);
        w24_g[n][kt][qt] = make_uint4(b0h, b1h, b0l, b1l);
    }
}

__global__ void nca_init(const float* __restrict__ input) {
    int pix = blockIdx.x * blockDim.x + threadIdx.x;
    if (pix < NPIX) {
        float* g = g_bufs[0] + (size_t)pix * 16;
        g[0] = input[pix];
        #pragma unroll
        for (int c = 1; c < 16; c++) g[c] = 0.0f;
    }
}

// smem: raw (cp.async dst) 12672 B | haloS 12672 B | rawS 4096 B
#define OFF_HALOS 12672
#define OFF_RAWS  (12672 + 12672)
#define SMEM_BYTES (12672 + 12672 + 4096)   // 29440

// issue cp.async halo prefetch for image-row `row` into raw buffer
__device__ __forceinline__ void halo_prefetch(
    u32 rawA, const float* __restrict__ gsrc, int row, int tid)
{
    int bI = row >> 6, h0 = row & 63;
    #pragma unroll
    for (int it = 0; it < 13; it++) {
        int idx = tid + it * 128;
        if (idx < 1584) {
            int cell = idx >> 3, q8 = idx & 7;
            int rr = cell / 66, wc = cell - rr * 66;
            int hh = h0 + rr - 1, ww = wc - 1;
            bool ok = (hh >= 0) && (hh < Hdim) && (ww >= 0) && (ww < Wdim);
            const float* src = gsrc +
                ((size_t)((bI * Hdim + hh) * Wdim + ww) << 4) + 2 * q8;
            int srcsz = ok ? 8 : 0;
            asm volatile("cp.async.ca.shared.global [%0], [%1], 8, %2;"
                         :: "r"(rawA + idx * 8), "l"(src), "r"(srcsz) : "memory");
        }
    }
    asm volatile("cp.async.commit_group;" ::: "memory");
}

// Persistent CTA (128 thr / 4 warps, 4 CTAs/SM): rows bid, bid+592, ...
// Per row: split raw->haloS, prefetch next row via cp.async, compute, epilogue.
__global__ __launch_bounds__(128, 4) void nca_step_h(
    int sb, const float* __restrict__ cb, const float* __restrict__ b1,
    const float* __restrict__ b2)
{
    extern __shared__ unsigned char smb[];
    float2* raw   = (float2*)smb;
    uint2*  haloS = (uint2*)(smb + OFF_HALOS);
    float2* rawS  = (float2*)(smb + OFF_RAWS);
    u32 rawA;
    asm("{ .reg .u64 t; cvta.to.shared.u64 t, %1; cvt.u32.u64 %0, t; }"
        : "=r"(rawA) : "l"(smb));

    const float* __restrict__ gsrc = g_bufs[sb];
    float* __restrict__ gdst = g_bufs[sb ^ 1];

    const int tid  = threadIdx.x;
    const int lane = tid & 31;
    const int warp = tid >> 5;
    const int wp = warp * 16;
    const int qt = lane & 3, rt = lane >> 2;

    // hoisted fragment pointers
    const uint4* cwB = &cW4_g[0][rt][qt];            // +tap*512 +nt*32
    const uint4* w1B = &w14_g[0][0][rt][qt];         // +q*2048 +kt*256 +nt*32
    const uint4* w2B = (const uint4*)w24_g + rt * 64 + qt;  // +nt2*512 +kt2*4

    // prologue: prefetch first row
    halo_prefetch(rawA, gsrc, blockIdx.x, tid);

    for (int row = blockIdx.x; row < NROWS; row += GRID_P) {
        const int bI = row >> 6, h0 = row & 63;

        // ---- wait prefetch; split raw -> haloS (+ raw center row -> rawS) ----
        asm volatile("cp.async.wait_group 0;" ::: "memory");
        __syncthreads();
        #pragma unroll
        for (int it = 0; it < 13; it++) {
            int idx = tid + it * 128;
            if (idx < 1584) {
                float2 v = raw[idx];
                u32 hi, lo; splitpk(v.x, v.y, hi, lo);
                haloS[idx] = make_uint2(hi, lo);
                int cell = idx >> 3;
                int rr = cell / 66, wc = cell - rr * 66;
                if (rr == 1 && wc >= 1 && wc < 65)
                    rawS[(wc - 1) * 8 + (idx & 7)] = v;
            }
        }
        __syncthreads();

        // ---- prefetch next row into raw (now free); overlaps compute ----
        int nrow = row + GRID_P;
        if (nrow < NROWS) halo_prefetch(rawA, gsrc, nrow, tid);

        // ================= conv: m16 x n128 x K144 (all-n per warp) =========
        float acc[16][4];
        #pragma unroll
        for (int nt = 0; nt < 16; nt++) {
            int n0 = 8 * nt + 2 * qt;
            float bb0 = __ldg(cb + n0), bb1 = __ldg(cb + n0 + 1);
            acc[nt][0] = bb0; acc[nt][1] = bb1;
            acc[nt][2] = bb0; acc[nt][3] = bb1;
        }
        #pragma unroll
        for (int tap = 0; tap < 9; tap++) {
            const int ky = tap / 3, kx = tap - 3 * ky;
            int c0 = ky * 66 + wp + rt + kx;
            int c1 = c0 + 8;
            uint2 A0 = haloS[c0 * 8 + qt];
            uint2 A1 = haloS[c1 * 8 + qt];
            uint2 A2 = haloS[c0 * 8 + qt + 4];
            uint2 A3 = haloS[c1 * 8 + qt + 4];
            #pragma unroll
            for (int nt = 0; nt < 16; nt++) {
                uint4 Bv = __ldg(cwB + tap * 512 + nt * 32);
                mma_bf(acc[nt], A0.x, A1.x, A2.x, A3.x, Bv.x, Bv.y);
                mma_bf(acc[nt], A0.x, A1.x, A2.x, A3.x, Bv.z, Bv.w);
                mma_bf(acc[nt], A0.y, A1.y, A2.y, A3.y, Bv.x, Bv.y);
            }
        }

        // ---- h = relu(conv) -> d1 A-fragments, in registers ----
        u32 hh_[8][4], hl_[8][4];
        #pragma unroll
        for (int kt = 0; kt < 8; kt++) {
            float* cA = acc[2 * kt];
            float* cB = acc[2 * kt + 1];
            splitpk(fmaxf(cA[0], 0.f), fmaxf(cA[1], 0.f), hh_[kt][0], hl_[kt][0]);
            splitpk(fmaxf(cA[2], 0.f), fmaxf(cA[3], 0.f), hh_[kt][1], hl_[kt][1]);
            splitpk(fmaxf(cB[0], 0.f), fmaxf(cB[1], 0.f), hh_[kt][2], hl_[kt][2]);
            splitpk(fmaxf(cB[2], 0.f), fmaxf(cB[3], 0.f), hh_[kt][3], hl_[kt][3]);
        }

        // ============ d1 (m16 x n256 x k128, 4 n-passes) fused with d2 ========
        float acc2[2][4];
        #pragma unroll
        for (int nt2 = 0; nt2 < 2; nt2++)
            #pragma unroll
            for (int e = 0; e < 4; e++) acc2[nt2][e] = 0.f;

        #pragma unroll 2
        for (int q = 0; q < 4; q++) {
            float acc1[8][4];
            #pragma unroll
            for (int nt = 0; nt < 8; nt++) {
                int n0 = 64 * q + 8 * nt + 2 * qt;
                float bb0 = __ldg(b1 + n0), bb1 = __ldg(b1 + n0 + 1);
                acc1[nt][0] = bb0; acc1[nt][1] = bb1;
                acc1[nt][2] = bb0; acc1[nt][3] = bb1;
            }
            #pragma unroll
            for (int kt = 0; kt < 8; kt++) {
                #pragma unroll
                for (int nt = 0; nt < 8; nt++) {
                    uint4 Bv = __ldg(w1B + q * 2048 + kt * 256 + nt * 32);
                    mma_bf(acc1[nt], hh_[kt][0], hh_[kt][1], hh_[kt][2], hh_[kt][3], Bv.x, Bv.y);
                    mma_bf(acc1[nt], hh_[kt][0], hh_[kt][1], hh_[kt][2], hh_[kt][3], Bv.z, Bv.w);
                    mma_bf(acc1[nt], hl_[kt][0], hl_[kt][1], hl_[kt][2], hl_[kt][3], Bv.x, Bv.y);
                }
            }
            #pragma unroll
            for (int ktl = 0; ktl < 4; ktl++) {
                float* cA = acc1[2 * ktl];
                float* cB = acc1[2 * ktl + 1];
                u32 ah0, al0, ah1, al1, ah2, al2, ah3, al3;
                splitpk(fmaxf(cA[0], 0.f), fmaxf(cA[1], 0.f), ah0, al0);
                splitpk(fmaxf(cA[2], 0.f), fmaxf(cA[3], 0.f), ah1, al1);
                splitpk(fmaxf(cB[0], 0.f), fmaxf(cB[1], 0.f), ah2, al2);
                splitpk(fmaxf(cB[2], 0.f), fmaxf(cB[3], 0.f), ah3, al3);
                int kt2 = 4 * q + ktl;
                #pragma unroll
                for (int nt2 = 0; nt2 < 2; nt2++) {
                    uint4 Bv = __ldg(w2B + nt2 * 512 + kt2 * 4);
                    mma_bf(acc2[nt2], ah0, ah1, ah2, ah3, Bv.x, Bv.y);
                    mma_bf(acc2[nt2], ah0, ah1, ah2, ah3, Bv.z, Bv.w);
                    mma_bf(acc2[nt2], al0, al1, al2, al3, Bv.x, Bv.y);
                }
            }
        }

        // ---- masked residual update from rawS (smem) -> gdst ----
        #pragma unroll
        for (int half = 0; half < 2; half++) {
            int px = wp + rt + 8 * half;
            int P = (bI * Hdim + h0) * Wdim + px;
            bool alive = rawS[px * 8].x > 0.1f;
            #pragma unroll
            for (int nt2 = 0; nt2 < 2; nt2++) {
                int ch0 = 8 * nt2 + 2 * qt;
                float2 o = rawS[px * 8 + (ch0 >> 1)];
                float e0 = acc2[nt2][2 * half + 0];
                float e1 = acc2[nt2][2 * half + 1];
                float out0 = o.x, out1 = o.y;
                if (ch0 != 0 && alive) out0 += e0 + __ldg(b2 + ch0);
                if (alive)             out1 += e1 + __ldg(b2 + ch0 + 1);
                *(float2*)(gdst + (size_t)P * 16 + ch0) = make_float2(out0, out1);
            }
        }
        __syncthreads();   // rawS reads done before next row's split overwrites
    }
}

__global__ void nca_softmax(float* __restrict__ out) {
    int pix = blockIdx.x * blockDim.x + threadIdx.x;
    if (pix >= NPIX) return;
    const float* g = g_bufs[0] + (size_t)pix * 16;
    float v[10];
    #pragma unroll
    for (int c = 0; c < 10; c++) v[c] = g[1 + c];
    float mx = v[0];
    #pragma unroll
    for (int c = 1; c < 10; c++) mx = fmaxf(mx, v[c]);
    float s = 0.0f;
    #pragma unroll
    for (int c = 0; c < 10; c++) { v[c] = __expf(v[c] - mx); s += v[c]; }
    float inv = 1.0f / s;
    float* o = out + (size_t)pix * 10;
    #pragma unroll
    for (int c = 0; c < 10; c++) o[c] = v[c] * inv;
}

extern "C" void kernel_launch(void* const* d_in, const int* in_sizes, int n_in,
                              void* d_out, int out_size) {
    const float* input = (const float*)d_in[0];
    const float* cw    = (const float*)d_in[1];
    const float* cb    = (const float*)d_in[2];
    const float* w1    = (const float*)d_in[3];
    const float* b1    = (const float*)d_in[4];
    const float* w2    = (const float*)d_in[5];
    const float* b2    = (const float*)d_in[6];

    cudaFuncSetAttribute(nca_step_h, cudaFuncAttributeMaxDynamicSharedMemorySize, SMEM_BYTES);

    nca_prep<<<54, 256>>>(cw, w1, w2);
    nca_init<<<NPIX / 256, 256>>>(input);
    for (int t = 0; t < TSTEPS; t++) {
        nca_step_h<<<GRID_P, 128, SMEM_BYTES>>>(t & 1, cb, b1, b2);
    }
    nca_softmax<<<NPIX / 256, 256>>>((float*)d_out);
}

// round 16
// speedup vs baseline: 1.2296x; 1.2296x over previous
#include <cuda_runtime.h>
#include <cuda_bf16.h>

#define Bdim 64
#define Hdim 64
#define Wdim 64
#define NPIX (Bdim * Hdim * Wdim)
#define TSTEPS 60

typedef unsigned int u32;

__device__ float g_bufs[2][NPIX * 16];

// Weight fragment images, uint4 = {B0hi, B1hi, B0lo, B1lo} (one MMA B-frag pair).
__device__ __align__(16) uint4 cW4_g[9][128][4];     // [tap][n][qt]
__device__ __align__(16) uint4 w14_g[4][8][64][4];   // [quarter][kt][nl][qt]
__device__ __align__(16) uint4 w24_g[16][16][4];     // [n][kt2][qt]

__device__ __forceinline__ void splitpk(float x0, float x1, u32& hi, u32& lo) {
    u32 h;
    asm("cvt.rn.bf16x2.f32 %0, %1, %2;" : "=r"(h) : "f"(x1), "f"(x0));
    float r0 = x0 - __uint_as_float(h << 16);
    float r1 = x1 - __uint_as_float(h & 0xFFFF0000u);
    u32 l;
    asm("cvt.rn.bf16x2.f32 %0, %1, %2;" : "=r"(l) : "f"(r1), "f"(r0));
    hi = h; lo = l;
}

__device__ __forceinline__ void mma_bf(float* c, u32 a0, u32 a1, u32 a2, u32 a3,
                                       u32 b0, u32 b1) {
    asm volatile(
        "mma.sync.aligned.m16n8k16.row.col.f32.bf16.bf16.f32 "
        "{%0,%1,%2,%3}, {%4,%5,%6,%7}, {%8,%9}, {%0,%1,%2,%3};"
        : "+f"(c[0]), "+f"(c[1]), "+f"(c[2]), "+f"(c[3])
        : "r"(a0), "r"(a1), "r"(a2), "r"(a3), "r"(b0), "r"(b1));
}

// ---------------- prep: build fragment images (once) ----------------
__global__ void nca_prep(const float* __restrict__ cw, const float* __restrict__ w1,
                         const float* __restrict__ w2) {
    int idx = blockIdx.x * blockDim.x + threadIdx.x;
    if (idx < 4608) {                         // conv: 9 tap x 128 n x 4 qt
        int tap = idx >> 9, rem = idx & 511;
        int n = rem >> 2, qt = rem & 3;
        int k0 = 16 * tap + 2 * qt;
        float v0 = cw[k0 * 128 + n],       v1 = cw[(k0 + 1) * 128 + n];
        float v2 = cw[(k0 + 8) * 128 + n], v3 = cw[(k0 + 9) * 128 + n];
        u32 b0h, b0l, b1h, b1l;
        splitpk(v0, v1, b0h, b0l); splitpk(v2, v3, b1h, b1l);
        cW4_g[tap][n][qt] = make_uint4(b0h, b1h, b0l, b1l);
    } else if (idx < 4608 + 8192) {           // w1: 4 q x 8 kt x 64 nl x 4 qt
        int i = idx - 4608;
        int q = i >> 11, rem = i & 2047;
        int kt = rem >> 8, r2 = rem & 255, nl = r2 >> 2, qt = r2 & 3;
        int n = 64 * q + nl, k0 = 16 * kt + 2 * qt;
        float v0 = w1[k0 * 256 + n],       v1 = w1[(k0 + 1) * 256 + n];
        float v2 = w1[(k0 + 8) * 256 + n], v3 = w1[(k0 + 9) * 256 + n];
        u32 b0h, b0l, b1h, b1l;
        splitpk(v0, v1, b0h, b0l); splitpk(v2, v3, b1h, b1l);
        w14_g[q][kt][nl][qt] = make_uint4(b0h, b1h, b0l, b1l);
    } else if (idx < 4608 + 8192 + 1024) {    // w2: 16 n x 16 kt2 x 4 qt
        int i = idx - 12800;
        int n = i >> 6, r2 = i & 63, kt = r2 >> 2, qt = r2 & 3;
        int k0 = 16 * kt + 2 * qt;
        float v0 = w2[k0 * 16 + n],       v1 = w2[(k0 + 1) * 16 + n];
        float v2 = w2[(k0 + 8) * 16 + n], v3 = w2[(k0 + 9) * 16 + n];
        u32 b0h, b0l, b1h, b1l;
        splitpk(v0, v1, b0h, b0l); splitpk(v2, v3, b1h, b1l);
        w24_g[n][kt][qt] = make_uint4(b0h, b1h, b0l, b1l);
    }
}

__global__ void nca_init(const float* __restrict__ input) {
    int pix = blockIdx.x * blockDim.x + threadIdx.x;
    if (pix < NPIX) {
        float* g = g_bufs[0] + (size_t)pix * 16;
        g[0] = input[pix];
        #pragma unroll
        for (int c = 1; c < 16; c++) g[c] = 0.0f;
    }
}

// smem: haloS — 3 x 66 x 8 x uint2 = 12672 B; rawS — 64 x 8 x float2 = 4096 B
#define OFF_RAWS 12672
#define SMEM_BYTES (12672 + 4096)   // 16768

// CTA = 1 image row (64 px), 128 threads / 4 warps; warp owns m16 px end-to-end.
// 4 CTAs/SM. One __syncthreads (halo staging) only.
__global__ __launch_bounds__(128, 4) void nca_step_h(
    int sb, const float* __restrict__ cb, const float* __restrict__ b1,
    const float* __restrict__ b2)
{
    extern __shared__ unsigned char smb[];
    uint2*  haloS = (uint2*)smb;
    float2* rawS  = (float2*)(smb + OFF_RAWS);

    const float* __restrict__ gsrc = g_bufs[sb];
    float* __restrict__ gdst = g_bufs[sb ^ 1];

    const int tid  = threadIdx.x;
    const int lane = tid & 31;
    const int warp = tid >> 5;
    const int wp = warp * 16;            // pixel offset within row
    const int qt = lane & 3, rt = lane >> 2;
    const int bI = blockIdx.x >> 6;
    const int h0 = blockIdx.x & 63;

    // ---- conv accumulator init hoisted: cb loads overlap halo staging ----
    float acc[16][4];
    #pragma unroll
    for (int nt = 0; nt < 16; nt++) {
        float2 bb = *(const float2*)(cb + 8 * nt + 2 * qt);
        acc[nt][0] = bb.x; acc[nt][1] = bb.y;
        acc[nt][2] = bb.x; acc[nt][3] = bb.y;
    }

    // ---- halo staging: batched-load (MLP 13), then split+store ----
    {
        float2 v[13];
        #pragma unroll
        for (int it = 0; it < 13; it++) {
            int idx = tid + it * 128;
            v[it] = make_float2(0.f, 0.f);
            if (idx < 1584) {
                int cell = idx >> 3, q8 = idx & 7;
                int rr = cell / 66, wc = cell - rr * 66;
                int hh = h0 + rr - 1, ww = wc - 1;
                if (hh >= 0 && hh < Hdim && ww >= 0 && ww < Wdim)
                    v[it] = *(const float2*)(gsrc +
                        ((size_t)((bI * Hdim + hh) * Wdim + ww) << 4) + 2 * q8);
            }
        }
        #pragma unroll
        for (int it = 0; it < 13; it++) {
            int idx = tid + it * 128;
            if (idx < 1584) {
                u32 hi, lo; splitpk(v[it].x, v[it].y, hi, lo);
                haloS[idx] = make_uint2(hi, lo);
                int cell = idx >> 3;
                int rr = cell / 66, wc = cell - rr * 66;
                if (rr == 1 && wc >= 1 && wc < 65)     // cache raw center row
                    rawS[(wc - 1) * 8 + (idx & 7)] = v[it];
            }
        }
    }
    __syncthreads();

    // hoisted fragment pointers
    const uint4* cwB = &cW4_g[0][rt][qt];            // +tap*512 +nt*32
    const uint4* w1B = &w14_g[0][0][rt][qt];         // +q*2048 +kt*256 +nt*32
    const uint4* w2B = (const uint4*)w24_g + rt * 64 + qt;  // +nt2*512 +kt2*4

    // ================= conv: m16 x n128 x K144 (all-n per warp) =============
    #pragma unroll
    for (int tap = 0; tap < 9; tap++) {
        const int ky = tap / 3, kx = tap - 3 * ky;
        int c0 = ky * 66 + wp + rt + kx;
        int c1 = c0 + 8;
        uint2 A0 = haloS[c0 * 8 + qt];
        uint2 A1 = haloS[c1 * 8 + qt];
        uint2 A2 = haloS[c0 * 8 + qt + 4];
        uint2 A3 = haloS[c1 * 8 + qt + 4];
        #pragma unroll
        for (int nt = 0; nt < 16; nt++) {
            uint4 Bv = __ldg(cwB + tap * 512 + nt * 32);
            mma_bf(acc[nt], A0.x, A1.x, A2.x, A3.x, Bv.x, Bv.y);
            mma_bf(acc[nt], A0.x, A1.x, A2.x, A3.x, Bv.z, Bv.w);
            mma_bf(acc[nt], A0.y, A1.y, A2.y, A3.y, Bv.x, Bv.y);
        }
    }

    // ---- h = relu(conv) -> d1 A-fragments, entirely in registers ----
    u32 hh_[8][4], hl_[8][4];
    #pragma unroll
    for (int kt = 0; kt < 8; kt++) {
        float* cA = acc[2 * kt];
        float* cB = acc[2 * kt + 1];
        splitpk(fmaxf(cA[0], 0.f), fmaxf(cA[1], 0.f), hh_[kt][0], hl_[kt][0]);
        splitpk(fmaxf(cA[2], 0.f), fmaxf(cA[3], 0.f), hh_[kt][1], hl_[kt][1]);
        splitpk(fmaxf(cB[0], 0.f), fmaxf(cB[1], 0.f), hh_[kt][2], hl_[kt][2]);
        splitpk(fmaxf(cB[2], 0.f), fmaxf(cB[3], 0.f), hh_[kt][3], hl_[kt][3]);
    }

    // ============ d1 (m16 x n256 x k128, 4 n-passes) fused with d2 ============
    float acc2[2][4];
    #pragma unroll
    for (int nt2 = 0; nt2 < 2; nt2++)
        #pragma unroll
        for (int e = 0; e < 4; e++) acc2[nt2][e] = 0.f;

    #pragma unroll
    for (int q = 0; q < 4; q++) {
        float acc1[8][4];
        #pragma unroll
        for (int nt = 0; nt < 8; nt++) {
            float2 bb = *(const float2*)(b1 + 64 * q + 8 * nt + 2 * qt);
            acc1[nt][0] = bb.x; acc1[nt][1] = bb.y;
            acc1[nt][2] = bb.x; acc1[nt][3] = bb.y;
        }
        #pragma unroll
        for (int kt = 0; kt < 8; kt++) {
            #pragma unroll
            for (int nt = 0; nt < 8; nt++) {
                uint4 Bv = __ldg(w1B + q * 2048 + kt * 256 + nt * 32);
                mma_bf(acc1[nt], hh_[kt][0], hh_[kt][1], hh_[kt][2], hh_[kt][3], Bv.x, Bv.y);
                mma_bf(acc1[nt], hh_[kt][0], hh_[kt][1], hh_[kt][2], hh_[kt][3], Bv.z, Bv.w);
                mma_bf(acc1[nt], hl_[kt][0], hl_[kt][1], hl_[kt][2], hl_[kt][3], Bv.x, Bv.y);
            }
        }
        // a = relu(acc1) -> register A-frags -> d2 partial MMAs (kt2 = 4q + ktl)
        #pragma unroll
        for (int ktl = 0; ktl < 4; ktl++) {
            float* cA = acc1[2 * ktl];
            float* cB = acc1[2 * ktl + 1];
            u32 ah0, al0, ah1, al1, ah2, al2, ah3, al3;
            splitpk(fmaxf(cA[0], 0.f), fmaxf(cA[1], 0.f), ah0, al0);
            splitpk(fmaxf(cA[2], 0.f), fmaxf(cA[3], 0.f), ah1, al1);
            splitpk(fmaxf(cB[0], 0.f), fmaxf(cB[1], 0.f), ah2, al2);
            splitpk(fmaxf(cB[2], 0.f), fmaxf(cB[3], 0.f), ah3, al3);
            int kt2 = 4 * q + ktl;
            #pragma unroll
            for (int nt2 = 0; nt2 < 2; nt2++) {
                uint4 Bv = __ldg(w2B + nt2 * 512 + kt2 * 4);
                mma_bf(acc2[nt2], ah0, ah1, ah2, ah3, Bv.x, Bv.y);
                mma_bf(acc2[nt2], ah0, ah1, ah2, ah3, Bv.z, Bv.w);
                mma_bf(acc2[nt2], al0, al1, al2, al3, Bv.x, Bv.y);
            }
        }
    }

    // ---- masked residual update from rawS (smem) -> gdst ----
    #pragma unroll
    for (int half = 0; half < 2; half++) {
        int px = wp + rt + 8 * half;
        int P = (bI * Hdim + h0) * Wdim + px;
        bool alive = rawS[px * 8].x > 0.1f;
        #pragma unroll
        for (int nt2 = 0; nt2 < 2; nt2++) {
            int ch0 = 8 * nt2 + 2 * qt;
            float2 o = rawS[px * 8 + (ch0 >> 1)];
            float e0 = acc2[nt2][2 * half + 0];
            float e1 = acc2[nt2][2 * half + 1];
            float out0 = o.x, out1 = o.y;
            if (ch0 != 0 && alive) out0 += e0 + __ldg(b2 + ch0);
            if (alive)             out1 += e1 + __ldg(b2 + ch0 + 1);
            *(float2*)(gdst + (size_t)P * 16 + ch0) = make_float2(out0, out1);
        }
    }
}

__global__ void nca_softmax(float* __restrict__ out) {
    int pix = blockIdx.x * blockDim.x + threadIdx.x;
    if (pix >= NPIX) return;
    const float* g = g_bufs[0] + (size_t)pix * 16;
    float v[10];
    #pragma unroll
    for (int c = 0; c < 10; c++) v[c] = g[1 + c];
    float mx = v[0];
    #pragma unroll
    for (int c = 1; c < 10; c++) mx = fmaxf(mx, v[c]);
    float s = 0.0f;
    #pragma unroll
    for (int c = 0; c < 10; c++) { v[c] = __expf(v[c] - mx); s += v[c]; }
    float inv = 1.0f / s;
    float* o = out + (size_t)pix * 10;
    #pragma unroll
    for (int c = 0; c < 10; c++) o[c] = v[c] * inv;
}

extern "C" void kernel_launch(void* const* d_in, const int* in_sizes, int n_in,
                              void* d_out, int out_size) {
    const float* input = (const float*)d_in[0];
    const float* cw    = (const float*)d_in[1];
    const float* cb    = (const float*)d_in[2];
    const float* w1    = (const float*)d_in[3];
    const float* b1    = (const float*)d_in[4];
    const float* w2    = (const float*)d_in[5];
    const float* b2    = (const float*)d_in[6];

    cudaFuncSetAttribute(nca_step_h, cudaFuncAttributeMaxDynamicSharedMemorySize, SMEM_BYTES);

    nca_prep<<<54, 256>>>(cw, w1, w2);
    nca_init<<<NPIX / 256, 256>>>(input);
    for (int t = 0; t < TSTEPS; t++) {
        nca_step_h<<<Bdim * Hdim, 128, SMEM_BYTES>>>(t & 1, cb, b1, b2);
    }
    nca_softmax<<<NPIX / 256, 256>>>((float*)d_out);
}